// round 5
// baseline (speedup 1.0000x reference)
#include <cuda_runtime.h>
#include <math.h>
#include <stdint.h>

// ---------------- scratch (static device globals; no allocation) ----------------
__device__ float g_col[19267584];   // stage1 dsample col: 2*147*65536
__device__ float g_off[19267584];   // offset conv out (max stage1: 2*147*65536)
__device__ float g_tmp[8388608];    // pre-norm GEMM out (max stage1: 2*64*65536)
__device__ float g_a[2097152];
__device__ float g_b[2097152];
__device__ float g_mean[512];
__device__ float g_rstd[512];
__device__ float g_wpad[33760];     // stage-1 weights padded to lda=160
__device__ float4 g_pw4[524288];    // deform precomp weights (2*16*16384 max)
__device__ int4  g_pi4[524288];     // deform precomp indices
__device__ float g_psum[262144];    // per-(nc, colCTA) partial sums (512*512)
__device__ float g_psum2[262144];

#define MAXCOL 512

// ---------------- stage-1 deformable sampling -> column matrix ----------------
__global__ void deform_sample_kernel(const float* __restrict__ x,
                                     const float* __restrict__ off,
                                     float* __restrict__ col,
                                     int Cin, int H, int W, int KH, int KW,
                                     int stride, int pad, int Ho, int Wo)
{
    int npix = Ho * Wo;
    int pix = blockIdx.x * blockDim.x + threadIdx.x;
    if (pix >= npix) return;
    int K = KH * KW;
    int k = blockIdx.y;
    int n = blockIdx.z;
    int ho = pix / Wo, wo = pix % Wo;

    const float* offn = off + (size_t)n * 3 * K * npix;
    float oy = offn[(size_t)k * npix + pix];
    float ox = offn[(size_t)(K + k) * npix + pix];
    float ml = offn[(size_t)(2 * K + k) * npix + pix];
    float m = 1.0f / (1.0f + expf(-ml));

    int ky = k / KW, kx = k % KW;
    float py = (float)(ho * stride - pad + ky) + oy;
    float px = (float)(wo * stride - pad + kx) + ox;
    float y0f = floorf(py), x0f = floorf(px);
    int y0 = (int)y0f, x0 = (int)x0f;
    float wy = py - y0f, wx = px - x0f;

    int y1 = y0 + 1, x1 = x0 + 1;
    float vy0 = (y0 >= 0 && y0 <= H - 1) ? 1.0f : 0.0f;
    float vy1 = (y1 >= 0 && y1 <= H - 1) ? 1.0f : 0.0f;
    float vx0 = (x0 >= 0 && x0 <= W - 1) ? 1.0f : 0.0f;
    float vx1 = (x1 >= 0 && x1 <= W - 1) ? 1.0f : 0.0f;
    int y0c = min(max(y0, 0), H - 1), y1c = min(max(y1, 0), H - 1);
    int x0c = min(max(x0, 0), W - 1), x1c = min(max(x1, 0), W - 1);

    float w00 = (1.0f - wy) * (1.0f - wx) * vy0 * vx0 * m;
    float w01 = (1.0f - wy) * wx          * vy0 * vx1 * m;
    float w10 = wy          * (1.0f - wx) * vy1 * vx0 * m;
    float w11 = wy          * wx          * vy1 * vx1 * m;

    size_t b00 = (size_t)y0c * W + x0c;
    size_t b01 = (size_t)y0c * W + x1c;
    size_t b10 = (size_t)y1c * W + x0c;
    size_t b11 = (size_t)y1c * W + x1c;

    const float* xn = x + (size_t)n * Cin * H * W;
    float* cp = col + (size_t)n * Cin * K * npix + (size_t)k * npix + pix;
    size_t cstride = (size_t)K * npix;
    for (int c = 0; c < Cin; c++) {
        const float* xc = xn + (size_t)c * H * W;
        float v = w00 * xc[b00] + w01 * xc[b01] + w10 * xc[b10] + w11 * xc[b11];
        cp[(size_t)c * cstride] = v;
    }
}

// ---------------- deform precomp (stages 2/3, K=16): weights + indices ----------------
__global__ void deform_precomp_kernel(const float* __restrict__ off,
                                      float4* __restrict__ pw, int4* __restrict__ pi,
                                      int H, int W, int stride, int pad, int Ho, int Wo)
{
    int npix = Ho * Wo;
    int pix = blockIdx.x * blockDim.x + threadIdx.x;
    if (pix >= npix) return;
    const int K = 16, KW = 4;
    int k = blockIdx.y;
    int n = blockIdx.z;
    int ho = pix / Wo, wo = pix % Wo;

    const float* offn = off + (size_t)n * 3 * K * npix;
    float oy = offn[(size_t)k * npix + pix];
    float ox = offn[(size_t)(K + k) * npix + pix];
    float ml = offn[(size_t)(2 * K + k) * npix + pix];
    float m = 1.0f / (1.0f + expf(-ml));

    int ky = k / KW, kx = k % KW;
    float py = (float)(ho * stride - pad + ky) + oy;
    float px = (float)(wo * stride - pad + kx) + ox;
    float y0f = floorf(py), x0f = floorf(px);
    int y0 = (int)y0f, x0 = (int)x0f;
    float wy = py - y0f, wx = px - x0f;

    int y1 = y0 + 1, x1 = x0 + 1;
    float vy0 = (y0 >= 0 && y0 <= H - 1) ? 1.0f : 0.0f;
    float vy1 = (y1 >= 0 && y1 <= H - 1) ? 1.0f : 0.0f;
    float vx0 = (x0 >= 0 && x0 <= W - 1) ? 1.0f : 0.0f;
    float vx1 = (x1 >= 0 && x1 <= W - 1) ? 1.0f : 0.0f;
    int y0c = min(max(y0, 0), H - 1), y1c = min(max(y1, 0), H - 1);
    int x0c = min(max(x0, 0), W - 1), x1c = min(max(x1, 0), W - 1);

    float4 w;
    w.x = (1.0f - wy) * (1.0f - wx) * vy0 * vx0 * m;
    w.y = (1.0f - wy) * wx          * vy0 * vx1 * m;
    w.z = wy          * (1.0f - wx) * vy1 * vx0 * m;
    w.w = wy          * wx          * vy1 * vx1 * m;
    int4 id;
    id.x = y0c * W + x0c;
    id.y = y0c * W + x1c;
    id.z = y1c * W + x0c;
    id.w = y1c * W + x1c;
    size_t e = ((size_t)n * K + k) * npix + pix;
    pw[e] = w;
    pi[e] = id;
}

// ---------------- weight padding (stage 1: K=147 -> lda=160) ----------------
__global__ void pad_weights_kernel(const float* __restrict__ w, float* __restrict__ wp,
                                   int M, int K, int Kp)
{
    int idx = blockIdx.x * blockDim.x + threadIdx.x;
    if (idx >= M * Kp) return;
    int m = idx / Kp, k = idx % Kp;
    wp[idx] = (k < K) ? w[m * K + k] : 0.0f;
}

// ---------------- 3xTF32 implicit-conv / GEMM kernel ----------------
// MODE 0: B = precomputed col matrix [n][K][N]
// MODE 1: implicit conv, zero padding  (B = input tensor NCHW)
// MODE 2: implicit conv, reflect padding
// MODE 3: deformable conv via precomp weights/indices (K=16)
struct ConvGeom { int Cin, H, W, KH, KW, KKW, stride, pad, Wo; };

__device__ __forceinline__ uint32_t f2tf32(float f) {
    uint32_t r;
    asm("cvt.rna.tf32.f32 %0, %1;" : "=r"(r) : "f"(f));
    return r;
}
__device__ __forceinline__ void split_tf32(float f, uint32_t& hi, uint32_t& lo) {
    hi = f2tf32(f);
    float res = f - __uint_as_float(hi);
    lo = f2tf32(res);
}

#define AS_STRIDE 36
#define BS_STRIDE 136
#define BS_BUF (32 * BS_STRIDE)

extern __shared__ float smem_dyn[];

#define MMA_TF32(acc, a0, a1, a2, a3, b0, b1)                                  \
    asm volatile(                                                              \
        "mma.sync.aligned.m16n8k8.row.col.f32.tf32.tf32.f32 "                  \
        "{%0,%1,%2,%3}, {%4,%5,%6,%7}, {%8,%9}, {%0,%1,%2,%3};\n"              \
        : "+f"(acc[0]), "+f"(acc[1]), "+f"(acc[2]), "+f"(acc[3])               \
        : "r"(a0), "r"(a1), "r"(a2), "r"(a3), "r"(b0), "r"(b1))

template <int BM, int MODE, bool STATS>
__global__ void __launch_bounds__(256, 1)
gemm_conv_kernel(const float* __restrict__ A, int lda,
                 const float* __restrict__ B,
                 const float* __restrict__ bias,
                 float* __restrict__ C,
                 int M, int Kd, int N, ConvGeom g,
                 const float4* __restrict__ pw, const int4* __restrict__ pi,
                 float* __restrict__ psum, float* __restrict__ psum2)
{
    constexpr int AS_BUF = BM * AS_STRIDE;
    constexpr int IMAX = BM / 32;
    float* As = smem_dyn;
    float* Bs = smem_dyn + 2 * AS_BUF;
    constexpr int SW = STATS ? 4 : 1;
    __shared__ float s_sum[SW][BM][2];

    int nb = blockIdx.z;
    float* Cn = C + (size_t)nb * M * N;
    int bm = blockIdx.y * BM, bn = blockIdx.x * 128;
    int tid = threadIdx.x;
    int wid = tid >> 5, lane = tid & 31;
    int warp_m = (wid >> 2) * (BM / 2);
    int warp_n = (wid & 3) * 32;
    int lr = lane >> 2, lc = lane & 3;

    float acc[IMAX][4][4];
#pragma unroll
    for (int i = 0; i < IMAX; i++)
#pragma unroll
        for (int j = 0; j < 4; j++)
#pragma unroll
            for (int q = 0; q < 4; q++) acc[i][j][q] = 0.0f;

    int nk = (Kd + 31) / 32;

    auto loadA = [&](int kt, int s) {
        int k0 = kt * 32;
        constexpr int ACP = BM / 32;
#pragma unroll
        for (int t = 0; t < ACP; t++) {
            int idx = tid + t * 256;
            int m = idx >> 3;
            int k4 = (idx & 7) << 2;
            int gm = bm + m, gk = k0 + k4;
            const float* src = A + (size_t)gm * lda + gk;
            float* dst = As + s * AS_BUF + m * AS_STRIDE + k4;
            int bytes = (gm < M && gk < Kd) ? min(16, (Kd - gk) * 4) : 0;
            uint32_t sa = (uint32_t)__cvta_generic_to_shared(dst);
            asm volatile("cp.async.ca.shared.global [%0], [%1], 16, %2;\n"
                         :: "r"(sa), "l"(src), "r"(bytes));
        }
    };

    auto loadB_col = [&](int kt, int s) {
        const float* Bn = B + (size_t)nb * Kd * N;
        int k0 = kt * 32;
#pragma unroll
        for (int t = 0; t < 4; t++) {
            int idx = tid + t * 256;
            int k = idx >> 5;
            int n4 = (idx & 31) << 2;
            int gk = k0 + k;
            const float* src = Bn + (size_t)gk * N + bn + n4;
            float* dst = Bs + s * BS_BUF + k * BS_STRIDE + n4;
            int bytes = (gk < Kd) ? 16 : 0;
            uint32_t sa = (uint32_t)__cvta_generic_to_shared(dst);
            asm volatile("cp.async.ca.shared.global [%0], [%1], 16, %2;\n"
                         :: "r"(sa), "l"(src), "r"(bytes));
        }
    };

    // gather B tile: thread -> one k-row, 16 contiguous columns
    auto gatherB = [&](int kt, float* pref) {
        int k_l = tid >> 3;
        int cb = (tid & 7) << 4;
        int gk = kt * 32 + k_l;
        if (MODE == 3) {
            int c = gk >> 4;           // K = 16
            int kk = gk & 15;
            const float* xc = B + ((size_t)nb * g.Cin + c) * g.H * g.W;
            size_t e = ((size_t)nb * 16 + kk) * (size_t)N + bn + cb;
#pragma unroll
            for (int i = 0; i < 16; i++) {
                float4 w = __ldg(pw + e + i);
                int4 id = __ldg(pi + e + i);
                pref[i] = w.x * __ldg(xc + id.x) + w.y * __ldg(xc + id.y)
                        + w.z * __ldg(xc + id.z) + w.w * __ldg(xc + id.w);
            }
            return;
        }
        bool kv = gk < Kd;
        int kk = kv ? gk : 0;
        int c = kk / g.KKW;
        int r = kk - c * g.KKW;
        int ky = r / g.KW;
        int kx = r - ky * g.KW;
        int pix = bn + cb;
        int ho = pix / g.Wo;
        int wo = pix - ho * g.Wo;
        int iy = ho * g.stride - g.pad + ky;
        int ix0 = wo * g.stride - g.pad + kx;
        const float* xc = B + ((size_t)nb * g.Cin + c) * g.H * g.W;
        if (MODE == 2) {
            if (iy < 0) iy = -iy; else if (iy >= g.H) iy = 2 * g.H - 2 - iy;
            const float* rowp = xc + (size_t)iy * g.W;
#pragma unroll
            for (int i = 0; i < 16; i++) {
                int ix = ix0 + i * g.stride;
                if (ix < 0) ix = -ix; else if (ix >= g.W) ix = 2 * g.W - 2 - ix;
                pref[i] = kv ? __ldg(rowp + ix) : 0.0f;
            }
        } else {
            bool rok = kv && iy >= 0 && iy < g.H;
            const float* rowp = xc + (size_t)max(iy, 0) * g.W;
#pragma unroll
            for (int i = 0; i < 16; i++) {
                int ix = ix0 + i * g.stride;
                pref[i] = (rok && ix >= 0 && ix < g.W) ? __ldg(rowp + ix) : 0.0f;
            }
        }
    };
    auto stsB = [&](const float* pref, int s) {
        int k_l = tid >> 3;
        int cb = (tid & 7) << 4;
        float* dst = Bs + s * BS_BUF + k_l * BS_STRIDE + cb;
#pragma unroll
        for (int i = 0; i < 16; i++) dst[i] = pref[i];
    };

    loadA(0, 0);
    if (MODE == 0) {
        loadB_col(0, 0);
    } else {
        float pref[16];
        gatherB(0, pref);
        stsB(pref, 0);
    }
    asm volatile("cp.async.commit_group;\n");

    for (int kt = 0; kt < nk; kt++) {
        int s = kt & 1;
        float pref[16];
        bool do_pref = (kt + 1 < nk);
        if (do_pref) {
            loadA(kt + 1, s ^ 1);
            if (MODE == 0) loadB_col(kt + 1, s ^ 1);
            asm volatile("cp.async.commit_group;\n");
            if (MODE != 0) gatherB(kt + 1, pref);
            asm volatile("cp.async.wait_group 1;\n");
        } else {
            asm volatile("cp.async.wait_group 0;\n");
        }
        __syncthreads();

        const float* Asb = As + s * AS_BUF;
        const float* Bsb = Bs + s * BS_BUF;
#pragma unroll
        for (int ks = 0; ks < 4; ks++) {
            uint32_t ah[IMAX][4], al[IMAX][4], bh[4][2], bl[4][2];
#pragma unroll
            for (int i = 0; i < IMAX; i++) {
                const float* ap = Asb + (warp_m + i * 16 + lr) * AS_STRIDE + ks * 8 + lc;
                split_tf32(ap[0],                 ah[i][0], al[i][0]);
                split_tf32(ap[8 * AS_STRIDE],     ah[i][1], al[i][1]);
                split_tf32(ap[4],                 ah[i][2], al[i][2]);
                split_tf32(ap[8 * AS_STRIDE + 4], ah[i][3], al[i][3]);
            }
#pragma unroll
            for (int j = 0; j < 4; j++) {
                const float* bp = Bsb + (ks * 8 + lc) * BS_STRIDE + warp_n + j * 8 + lr;
                split_tf32(bp[0],             bh[j][0], bl[j][0]);
                split_tf32(bp[4 * BS_STRIDE], bh[j][1], bl[j][1]);
            }
#pragma unroll
            for (int i = 0; i < IMAX; i++)
#pragma unroll
                for (int j = 0; j < 4; j++) {
                    MMA_TF32(acc[i][j], ah[i][0], ah[i][1], ah[i][2], ah[i][3],
                             bl[j][0], bl[j][1]);
                    MMA_TF32(acc[i][j], al[i][0], al[i][1], al[i][2], al[i][3],
                             bh[j][0], bh[j][1]);
                    MMA_TF32(acc[i][j], ah[i][0], ah[i][1], ah[i][2], ah[i][3],
                             bh[j][0], bh[j][1]);
                }
        }
        if (MODE != 0 && do_pref) stsB(pref, s ^ 1);
        __syncthreads();
    }

    // ---- epilogue: bias + store (+ optional per-row partial stats) ----
#pragma unroll
    for (int i = 0; i < IMAX; i++) {
        int r0l = warp_m + i * 16 + lr;
        int r1l = r0l + 8;
        int gr0 = bm + r0l, gr1 = bm + r1l;
        float bv0 = (gr0 < M) ? bias[gr0] : 0.0f;
        float bv1 = (gr1 < M) ? bias[gr1] : 0.0f;
        float s0 = 0, q0 = 0, s1 = 0, q1 = 0;
#pragma unroll
        for (int j = 0; j < 4; j++) {
            int cidx = bn + warp_n + j * 8 + lc * 2;
            float v0 = acc[i][j][0] + bv0, v1 = acc[i][j][1] + bv0;
            float v2 = acc[i][j][2] + bv1, v3 = acc[i][j][3] + bv1;
            if (gr0 < M) *(float2*)&Cn[(size_t)gr0 * N + cidx] = make_float2(v0, v1);
            if (gr1 < M) *(float2*)&Cn[(size_t)gr1 * N + cidx] = make_float2(v2, v3);
            if (STATS) {
                s0 += v0 + v1; q0 += v0 * v0 + v1 * v1;
                s1 += v2 + v3; q1 += v2 * v2 + v3 * v3;
            }
        }
        if (STATS) {
            s0 += __shfl_xor_sync(0xffffffff, s0, 1); s0 += __shfl_xor_sync(0xffffffff, s0, 2);
            q0 += __shfl_xor_sync(0xffffffff, q0, 1); q0 += __shfl_xor_sync(0xffffffff, q0, 2);
            s1 += __shfl_xor_sync(0xffffffff, s1, 1); s1 += __shfl_xor_sync(0xffffffff, s1, 2);
            q1 += __shfl_xor_sync(0xffffffff, q1, 1); q1 += __shfl_xor_sync(0xffffffff, q1, 2);
            if (lc == 0) {
                s_sum[wid & 3][r0l][0] = s0; s_sum[wid & 3][r0l][1] = q0;
                s_sum[wid & 3][r1l][0] = s1; s_sum[wid & 3][r1l][1] = q1;
            }
        }
    }
    if (STATS) {
        __syncthreads();
        if (tid < BM) {
            int gm = bm + tid;
            if (gm < M) {
                float s = s_sum[0][tid][0] + s_sum[1][tid][0] + s_sum[2][tid][0] + s_sum[3][tid][0];
                float q = s_sum[0][tid][1] + s_sum[1][tid][1] + s_sum[2][tid][1] + s_sum[3][tid][1];
                size_t nc = (size_t)nb * M + gm;
                psum[nc * MAXCOL + blockIdx.x] = s;
                psum2[nc * MAXCOL + blockIdx.x] = q;
            }
        }
    }
}

// ---------------- finalize stats (deterministic tree) ----------------
__global__ void finalize_stats_kernel(const float* __restrict__ ps,
                                      const float* __restrict__ ps2,
                                      float* __restrict__ mean, float* __restrict__ rstd,
                                      int ncol, int npix)
{
    int nc = blockIdx.x;
    double s = 0.0, s2 = 0.0;
    for (int j = threadIdx.x; j < ncol; j += 128) {
        s += (double)ps[(size_t)nc * MAXCOL + j];
        s2 += (double)ps2[(size_t)nc * MAXCOL + j];
    }
    __shared__ double sh[128], sh2[128];
    sh[threadIdx.x] = s; sh2[threadIdx.x] = s2;
    __syncthreads();
    for (int o = 64; o > 0; o >>= 1) {
        if (threadIdx.x < o) { sh[threadIdx.x] += sh[threadIdx.x + o]; sh2[threadIdx.x] += sh2[threadIdx.x + o]; }
        __syncthreads();
    }
    if (threadIdx.x == 0) {
        double mn = sh[0] / npix;
        double var = sh2[0] / npix - mn * mn;
        mean[nc] = (float)mn;
        rstd[nc] = (float)rsqrt(var + 1e-5);
    }
}

// ---------------- instance norm: apply ----------------
__global__ void norm_apply_kernel(const float* __restrict__ x,
                                  const float* __restrict__ mean,
                                  const float* __restrict__ rstd,
                                  const float* __restrict__ skip,
                                  float* __restrict__ out,
                                  int npix, int relu, size_t total)
{
    size_t i = (size_t)blockIdx.x * blockDim.x + threadIdx.x;
    if (i >= total) return;
    int nc = (int)(i / (size_t)npix);
    float v = (x[i] - mean[nc]) * rstd[nc];
    if (skip) v += skip[i];
    if (relu) v = fmaxf(v, 0.0f);
    out[i] = v;
}

// ---------------- launch ----------------
static inline int smem_for(int BM) { return (2 * BM * AS_STRIDE + 2 * BS_BUF) * 4; }

extern "C" void kernel_launch(void* const* d_in, const int* in_sizes, int n_in,
                              void* d_out, int out_size)
{
    (void)in_sizes; (void)n_in; (void)out_size;
    const float* x      = (const float*)d_in[0];
    const float* off1_w = (const float*)d_in[1];
    const float* off1_b = (const float*)d_in[2];
    const float* dcn1_w = (const float*)d_in[3];
    const float* dcn1_b = (const float*)d_in[4];
    const float* off2_w = (const float*)d_in[5];
    const float* off2_b = (const float*)d_in[6];
    const float* dcn2_w = (const float*)d_in[7];
    const float* dcn2_b = (const float*)d_in[8];
    const float* off3_w = (const float*)d_in[9];
    const float* off3_b = (const float*)d_in[10];
    const float* dcn3_w = (const float*)d_in[11];
    const float* dcn3_b = (const float*)d_in[12];
    const float* rb1_w1 = (const float*)d_in[13];
    const float* rb1_b1 = (const float*)d_in[14];
    const float* rb1_w2 = (const float*)d_in[15];
    const float* rb1_b2 = (const float*)d_in[16];
    const float* rb2_w1 = (const float*)d_in[17];
    const float* rb2_b1 = (const float*)d_in[18];
    const float* rb2_w2 = (const float*)d_in[19];
    const float* rb2_b2 = (const float*)d_in[20];

    float* outp  = (float*)d_out;
    float* out_h = outp;
    float* skip1 = outp + 2097152;
    float* skip2 = outp + 2097152 + 8388608;

    float *col, *offb, *tmp, *ga, *gb, *mn, *rs, *wpad, *psum, *psum2;
    float4* pw; int4* pi;
    cudaGetSymbolAddress((void**)&col,  g_col);
    cudaGetSymbolAddress((void**)&offb, g_off);
    cudaGetSymbolAddress((void**)&tmp,  g_tmp);
    cudaGetSymbolAddress((void**)&ga,   g_a);
    cudaGetSymbolAddress((void**)&gb,   g_b);
    cudaGetSymbolAddress((void**)&mn,   g_mean);
    cudaGetSymbolAddress((void**)&rs,   g_rstd);
    cudaGetSymbolAddress((void**)&wpad, g_wpad);
    cudaGetSymbolAddress((void**)&pw,   g_pw4);
    cudaGetSymbolAddress((void**)&pi,   g_pi4);
    cudaGetSymbolAddress((void**)&psum, g_psum);
    cudaGetSymbolAddress((void**)&psum2, g_psum2);
    float* off1p = wpad;
    float* dcn1p = wpad + 147 * 160;

    static bool attr_set = false;
    if (!attr_set) {
        cudaFuncSetAttribute((const void*)gemm_conv_kernel<64, 0, true>,   cudaFuncAttributeMaxDynamicSharedMemorySize, smem_for(64));
        cudaFuncSetAttribute((const void*)gemm_conv_kernel<64, 1, false>,  cudaFuncAttributeMaxDynamicSharedMemorySize, smem_for(64));
        cudaFuncSetAttribute((const void*)gemm_conv_kernel<128, 2, true>,  cudaFuncAttributeMaxDynamicSharedMemorySize, smem_for(128));
        cudaFuncSetAttribute((const void*)gemm_conv_kernel<128, 3, true>,  cudaFuncAttributeMaxDynamicSharedMemorySize, smem_for(128));
        attr_set = true;
    }

    ConvGeom g0 = {};

    auto inorm = [&](const float* xin, float* dst, int C, int npix,
                     const float* skip, int relu) {
        finalize_stats_kernel<<<2 * C, 128>>>(psum, psum2, mn, rs, npix / 128, npix);
        size_t total = (size_t)2 * C * npix;
        norm_apply_kernel<<<(unsigned)((total + 255) / 256), 256>>>(xin, mn, rs, skip, dst, npix, relu, total);
    };

    // pack stage-1 weights
    pad_weights_kernel<<<(147 * 160 + 255) / 256, 256>>>(off1_w, off1p, 147, 147, 160);
    pad_weights_kernel<<<(64 * 160 + 255) / 256, 256>>>(dcn1_w, dcn1p, 64, 147, 160);

    // ===== Stage 1: mdcp(x, 7x7, s1, p3), 3 -> 64, 256x256 =====
    ConvGeom g1 = {3, 256, 256, 7, 7, 49, 1, 3, 256};
    gemm_conv_kernel<64, 1, false><<<dim3(512, 3, 2), 256, smem_for(64)>>>(
        off1p, 160, x, off1_b, offb, 147, 147, 65536, g1, nullptr, nullptr, nullptr, nullptr);
    {
        dim3 grid(65536 / 256, 49, 2);
        deform_sample_kernel<<<grid, 256>>>(x, offb, col, 3, 256, 256, 7, 7, 1, 3, 256, 256);
    }
    gemm_conv_kernel<64, 0, true><<<dim3(512, 1, 2), 256, smem_for(64)>>>(
        dcn1p, 160, col, dcn1_b, tmp, 64, 147, 65536, g0, nullptr, nullptr, psum, psum2);
    inorm(tmp, skip1, 64, 65536, nullptr, 1);

    // ===== Stage 2: mdcp(h1, 4x4, s2, p1), 64 -> 128, 128x128 =====
    ConvGeom g2 = {64, 256, 256, 4, 4, 16, 2, 1, 128};
    gemm_conv_kernel<64, 1, false><<<dim3(128, 1, 2), 256, smem_for(64)>>>(
        off2_w, 1024, skip1, off2_b, offb, 48, 1024, 16384, g2, nullptr, nullptr, nullptr, nullptr);
    deform_precomp_kernel<<<dim3(16384 / 256, 16, 2), 256>>>(offb, pw, pi, 256, 256, 2, 1, 128, 128);
    gemm_conv_kernel<128, 3, true><<<dim3(128, 1, 2), 256, smem_for(128)>>>(
        dcn2_w, 1024, skip1, dcn2_b, tmp, 128, 1024, 16384, g2, pw, pi, psum, psum2);
    inorm(tmp, skip2, 128, 16384, nullptr, 1);

    // ===== Stage 3: mdcp(h2, 4x4, s2, p1), 128 -> 256, 64x64 =====
    ConvGeom g3 = {128, 128, 128, 4, 4, 16, 2, 1, 64};
    gemm_conv_kernel<64, 1, false><<<dim3(32, 1, 2), 256, smem_for(64)>>>(
        off3_w, 2048, skip2, off3_b, offb, 48, 2048, 4096, g3, nullptr, nullptr, nullptr, nullptr);
    deform_precomp_kernel<<<dim3(4096 / 256, 16, 2), 256>>>(offb, pw, pi, 128, 128, 2, 1, 64, 64);
    gemm_conv_kernel<128, 3, true><<<dim3(32, 2, 2), 256, smem_for(128)>>>(
        dcn3_w, 2048, skip2, dcn3_b, tmp, 256, 2048, 4096, g3, pw, pi, psum, psum2);
    inorm(tmp, ga, 256, 4096, nullptr, 1);

    // ===== Res blocks (reflect-pad 3x3 convs, 256 ch, 64x64, implicit) =====
    ConvGeom gr = {256, 64, 64, 3, 3, 9, 1, 1, 64};
    gemm_conv_kernel<128, 2, true><<<dim3(32, 2, 2), 256, smem_for(128)>>>(
        rb1_w1, 2304, ga, rb1_b1, tmp, 256, 2304, 4096, gr, nullptr, nullptr, psum, psum2);
    inorm(tmp, gb, 256, 4096, nullptr, 1);
    gemm_conv_kernel<128, 2, true><<<dim3(32, 2, 2), 256, smem_for(128)>>>(
        rb1_w2, 2304, gb, rb1_b2, tmp, 256, 2304, 4096, gr, nullptr, nullptr, psum, psum2);
    inorm(tmp, ga, 256, 4096, ga, 0);

    gemm_conv_kernel<128, 2, true><<<dim3(32, 2, 2), 256, smem_for(128)>>>(
        rb2_w1, 2304, ga, rb2_b1, tmp, 256, 2304, 4096, gr, nullptr, nullptr, psum, psum2);
    inorm(tmp, gb, 256, 4096, nullptr, 1);
    gemm_conv_kernel<128, 2, true><<<dim3(32, 2, 2), 256, smem_for(128)>>>(
        rb2_w2, 2304, gb, rb2_b2, tmp, 256, 2304, 4096, gr, nullptr, nullptr, psum, psum2);
    inorm(tmp, out_h, 256, 4096, ga, 0);
}

// round 6
// speedup vs baseline: 1.3791x; 1.3791x over previous
#include <cuda_runtime.h>
#include <math.h>
#include <stdint.h>

// ---------------- scratch (static device globals; no allocation) ----------------
__device__ float g_col[33554432];   // dsample cols (max stage2: 2*1024*16384)
__device__ float g_off[19267584];   // offset conv out (max stage1: 2*147*65536)
__device__ float g_tmp[8388608];    // pre-norm GEMM out (max stage1: 2*64*65536)
__device__ float g_a[2097152];
__device__ float g_b[2097152];
__device__ float g_mean[512];
__device__ float g_rstd[512];
__device__ float g_wpad[33760];     // stage-1 weights padded to lda=160
__device__ float g_psum[262144];    // per-(nc, colCTA) partial sums (512*512)
__device__ float g_psum2[262144];

#define MAXCOL 512

// ---------------- deformable sampling -> column matrix ----------------
__global__ void deform_sample_kernel(const float* __restrict__ x,
                                     const float* __restrict__ off,
                                     float* __restrict__ col,
                                     int Cin, int H, int W, int KH, int KW,
                                     int stride, int pad, int Ho, int Wo)
{
    int npix = Ho * Wo;
    int pix = blockIdx.x * blockDim.x + threadIdx.x;
    if (pix >= npix) return;
    int K = KH * KW;
    int k = blockIdx.y;
    int n = blockIdx.z;
    int ho = pix / Wo, wo = pix % Wo;

    const float* offn = off + (size_t)n * 3 * K * npix;
    float oy = offn[(size_t)k * npix + pix];
    float ox = offn[(size_t)(K + k) * npix + pix];
    float ml = offn[(size_t)(2 * K + k) * npix + pix];
    float m = 1.0f / (1.0f + expf(-ml));

    int ky = k / KW, kx = k % KW;
    float py = (float)(ho * stride - pad + ky) + oy;
    float px = (float)(wo * stride - pad + kx) + ox;
    float y0f = floorf(py), x0f = floorf(px);
    int y0 = (int)y0f, x0 = (int)x0f;
    float wy = py - y0f, wx = px - x0f;

    int y1 = y0 + 1, x1 = x0 + 1;
    float vy0 = (y0 >= 0 && y0 <= H - 1) ? 1.0f : 0.0f;
    float vy1 = (y1 >= 0 && y1 <= H - 1) ? 1.0f : 0.0f;
    float vx0 = (x0 >= 0 && x0 <= W - 1) ? 1.0f : 0.0f;
    float vx1 = (x1 >= 0 && x1 <= W - 1) ? 1.0f : 0.0f;
    int y0c = min(max(y0, 0), H - 1), y1c = min(max(y1, 0), H - 1);
    int x0c = min(max(x0, 0), W - 1), x1c = min(max(x1, 0), W - 1);

    float w00 = (1.0f - wy) * (1.0f - wx) * vy0 * vx0 * m;
    float w01 = (1.0f - wy) * wx          * vy0 * vx1 * m;
    float w10 = wy          * (1.0f - wx) * vy1 * vx0 * m;
    float w11 = wy          * wx          * vy1 * vx1 * m;

    size_t b00 = (size_t)y0c * W + x0c;
    size_t b01 = (size_t)y0c * W + x1c;
    size_t b10 = (size_t)y1c * W + x0c;
    size_t b11 = (size_t)y1c * W + x1c;

    const float* xn = x + (size_t)n * Cin * H * W;
    float* cp = col + (size_t)n * Cin * K * npix + (size_t)k * npix + pix;
    size_t cstride = (size_t)K * npix;
    for (int c = 0; c < Cin; c++) {
        const float* xc = xn + (size_t)c * H * W;
        float v = w00 * xc[b00] + w01 * xc[b01] + w10 * xc[b10] + w11 * xc[b11];
        cp[(size_t)c * cstride] = v;
    }
}

// ---------------- weight padding (stage 1: K=147 -> lda=160) ----------------
__global__ void pad_weights_kernel(const float* __restrict__ w, float* __restrict__ wp,
                                   int M, int K, int Kp)
{
    int idx = blockIdx.x * blockDim.x + threadIdx.x;
    if (idx >= M * Kp) return;
    int m = idx / Kp, k = idx % Kp;
    wp[idx] = (k < K) ? w[m * K + k] : 0.0f;
}

// ---------------- 3xTF32 implicit-conv / GEMM kernel ----------------
// MODE 0: B = precomputed col matrix [n][K][N]
// MODE 1: implicit conv, zero padding  (B = input tensor NCHW)
// MODE 2: implicit conv, reflect padding
struct ConvGeom { int Cin, H, W, KH, KW, KKW, stride, pad, Wo; };

__device__ __forceinline__ uint32_t f2tf32(float f) {
    uint32_t r;
    asm("cvt.rna.tf32.f32 %0, %1;" : "=r"(r) : "f"(f));
    return r;
}
__device__ __forceinline__ void split_tf32(float f, uint32_t& hi, uint32_t& lo) {
    hi = f2tf32(f);
    float res = f - __uint_as_float(hi);
    lo = f2tf32(res);
}

#define AS_STRIDE 36
#define BS_STRIDE 136
#define BS_BUF (32 * BS_STRIDE)

extern __shared__ float smem_dyn[];

#define MMA_TF32(acc, a0, a1, a2, a3, b0, b1)                                  \
    asm volatile(                                                              \
        "mma.sync.aligned.m16n8k8.row.col.f32.tf32.tf32.f32 "                  \
        "{%0,%1,%2,%3}, {%4,%5,%6,%7}, {%8,%9}, {%0,%1,%2,%3};\n"              \
        : "+f"(acc[0]), "+f"(acc[1]), "+f"(acc[2]), "+f"(acc[3])               \
        : "r"(a0), "r"(a1), "r"(a2), "r"(a3), "r"(b0), "r"(b1))

template <int BM, int MODE, bool STATS>
__global__ void __launch_bounds__(256, 1)
gemm_conv_kernel(const float* __restrict__ A, int lda,
                 const float* __restrict__ B,
                 const float* __restrict__ bias,
                 float* __restrict__ C,
                 int M, int Kd, int N, ConvGeom g,
                 float* __restrict__ psum, float* __restrict__ psum2)
{
    constexpr int AS_BUF = BM * AS_STRIDE;
    constexpr int IMAX = BM / 32;
    float* As = smem_dyn;
    float* Bs = smem_dyn + 2 * AS_BUF;
    constexpr int SW = STATS ? 4 : 1;
    __shared__ float s_sum[SW][BM][2];

    int nb = blockIdx.z;
    float* Cn = C + (size_t)nb * M * N;
    int bm = blockIdx.y * BM, bn = blockIdx.x * 128;
    int tid = threadIdx.x;
    int wid = tid >> 5, lane = tid & 31;
    int warp_m = (wid >> 2) * (BM / 2);
    int warp_n = (wid & 3) * 32;
    int lr = lane >> 2, lc = lane & 3;

    float acc[IMAX][4][4];
#pragma unroll
    for (int i = 0; i < IMAX; i++)
#pragma unroll
        for (int j = 0; j < 4; j++)
#pragma unroll
            for (int q = 0; q < 4; q++) acc[i][j][q] = 0.0f;

    int nk = (Kd + 31) / 32;

    auto loadA = [&](int kt, int s) {
        int k0 = kt * 32;
        constexpr int ACP = BM / 32;
#pragma unroll
        for (int t = 0; t < ACP; t++) {
            int idx = tid + t * 256;
            int m = idx >> 3;
            int k4 = (idx & 7) << 2;
            int gm = bm + m, gk = k0 + k4;
            const float* src = A + (size_t)gm * lda + gk;
            float* dst = As + s * AS_BUF + m * AS_STRIDE + k4;
            int bytes = (gm < M && gk < Kd) ? min(16, (Kd - gk) * 4) : 0;
            uint32_t sa = (uint32_t)__cvta_generic_to_shared(dst);
            asm volatile("cp.async.ca.shared.global [%0], [%1], 16, %2;\n"
                         :: "r"(sa), "l"(src), "r"(bytes));
        }
    };

    auto loadB_col = [&](int kt, int s) {
        const float* Bn = B + (size_t)nb * Kd * N;
        int k0 = kt * 32;
#pragma unroll
        for (int t = 0; t < 4; t++) {
            int idx = tid + t * 256;
            int k = idx >> 5;
            int n4 = (idx & 31) << 2;
            int gk = k0 + k;
            const float* src = Bn + (size_t)gk * N + bn + n4;
            float* dst = Bs + s * BS_BUF + k * BS_STRIDE + n4;
            int bytes = (gk < Kd) ? 16 : 0;
            uint32_t sa = (uint32_t)__cvta_generic_to_shared(dst);
            asm volatile("cp.async.ca.shared.global [%0], [%1], 16, %2;\n"
                         :: "r"(sa), "l"(src), "r"(bytes));
        }
    };

    // gather B tile (implicit conv): thread -> one k-row, 16 contiguous columns
    auto gatherB = [&](int kt, float* pref) {
        int k_l = tid >> 3;
        int cb = (tid & 7) << 4;
        int gk = kt * 32 + k_l;
        bool kv = gk < Kd;
        int kk = kv ? gk : 0;
        int c = kk / g.KKW;
        int r = kk - c * g.KKW;
        int ky = r / g.KW;
        int kx = r - ky * g.KW;
        int pix = bn + cb;
        int ho = pix / g.Wo;
        int wo = pix - ho * g.Wo;
        int iy = ho * g.stride - g.pad + ky;
        int ix0 = wo * g.stride - g.pad + kx;
        const float* xc = B + ((size_t)nb * g.Cin + c) * g.H * g.W;
        if (MODE == 2) {
            if (iy < 0) iy = -iy; else if (iy >= g.H) iy = 2 * g.H - 2 - iy;
            const float* rowp = xc + (size_t)iy * g.W;
#pragma unroll
            for (int i = 0; i < 16; i++) {
                int ix = ix0 + i * g.stride;
                if (ix < 0) ix = -ix; else if (ix >= g.W) ix = 2 * g.W - 2 - ix;
                pref[i] = kv ? __ldg(rowp + ix) : 0.0f;
            }
        } else {
            bool rok = kv && iy >= 0 && iy < g.H;
            const float* rowp = xc + (size_t)max(iy, 0) * g.W;
#pragma unroll
            for (int i = 0; i < 16; i++) {
                int ix = ix0 + i * g.stride;
                pref[i] = (rok && ix >= 0 && ix < g.W) ? __ldg(rowp + ix) : 0.0f;
            }
        }
    };
    auto stsB = [&](const float* pref, int s) {
        int k_l = tid >> 3;
        int cb = (tid & 7) << 4;
        float* dst = Bs + s * BS_BUF + k_l * BS_STRIDE + cb;
#pragma unroll
        for (int i = 0; i < 16; i++) dst[i] = pref[i];
    };

    loadA(0, 0);
    if (MODE == 0) {
        loadB_col(0, 0);
    } else {
        float pref[16];
        gatherB(0, pref);
        stsB(pref, 0);
    }
    asm volatile("cp.async.commit_group;\n");

    for (int kt = 0; kt < nk; kt++) {
        int s = kt & 1;
        float pref[16];
        bool do_pref = (kt + 1 < nk);
        if (do_pref) {
            loadA(kt + 1, s ^ 1);
            if (MODE == 0) loadB_col(kt + 1, s ^ 1);
            asm volatile("cp.async.commit_group;\n");
            if (MODE != 0) gatherB(kt + 1, pref);
            asm volatile("cp.async.wait_group 1;\n");
        } else {
            asm volatile("cp.async.wait_group 0;\n");
        }
        __syncthreads();

        const float* Asb = As + s * AS_BUF;
        const float* Bsb = Bs + s * BS_BUF;
#pragma unroll
        for (int ks = 0; ks < 4; ks++) {
            uint32_t ah[IMAX][4], al[IMAX][4], bh[4][2], bl[4][2];
#pragma unroll
            for (int i = 0; i < IMAX; i++) {
                const float* ap = Asb + (warp_m + i * 16 + lr) * AS_STRIDE + ks * 8 + lc;
                split_tf32(ap[0],                 ah[i][0], al[i][0]);
                split_tf32(ap[8 * AS_STRIDE],     ah[i][1], al[i][1]);
                split_tf32(ap[4],                 ah[i][2], al[i][2]);
                split_tf32(ap[8 * AS_STRIDE + 4], ah[i][3], al[i][3]);
            }
#pragma unroll
            for (int j = 0; j < 4; j++) {
                const float* bp = Bsb + (ks * 8 + lc) * BS_STRIDE + warp_n + j * 8 + lr;
                split_tf32(bp[0],             bh[j][0], bl[j][0]);
                split_tf32(bp[4 * BS_STRIDE], bh[j][1], bl[j][1]);
            }
#pragma unroll
            for (int i = 0; i < IMAX; i++)
#pragma unroll
                for (int j = 0; j < 4; j++) {
                    MMA_TF32(acc[i][j], ah[i][0], ah[i][1], ah[i][2], ah[i][3],
                             bl[j][0], bl[j][1]);
                    MMA_TF32(acc[i][j], al[i][0], al[i][1], al[i][2], al[i][3],
                             bh[j][0], bh[j][1]);
                    MMA_TF32(acc[i][j], ah[i][0], ah[i][1], ah[i][2], ah[i][3],
                             bh[j][0], bh[j][1]);
                }
        }
        if (MODE != 0 && do_pref) stsB(pref, s ^ 1);
        __syncthreads();
    }

    // ---- epilogue: bias + store (+ optional per-row partial stats) ----
#pragma unroll
    for (int i = 0; i < IMAX; i++) {
        int r0l = warp_m + i * 16 + lr;
        int r1l = r0l + 8;
        int gr0 = bm + r0l, gr1 = bm + r1l;
        float bv0 = (gr0 < M) ? bias[gr0] : 0.0f;
        float bv1 = (gr1 < M) ? bias[gr1] : 0.0f;
        float s0 = 0, q0 = 0, s1 = 0, q1 = 0;
#pragma unroll
        for (int j = 0; j < 4; j++) {
            int cidx = bn + warp_n + j * 8 + lc * 2;
            float v0 = acc[i][j][0] + bv0, v1 = acc[i][j][1] + bv0;
            float v2 = acc[i][j][2] + bv1, v3 = acc[i][j][3] + bv1;
            if (gr0 < M) *(float2*)&Cn[(size_t)gr0 * N + cidx] = make_float2(v0, v1);
            if (gr1 < M) *(float2*)&Cn[(size_t)gr1 * N + cidx] = make_float2(v2, v3);
            if (STATS) {
                s0 += v0 + v1; q0 += v0 * v0 + v1 * v1;
                s1 += v2 + v3; q1 += v2 * v2 + v3 * v3;
            }
        }
        if (STATS) {
            s0 += __shfl_xor_sync(0xffffffff, s0, 1); s0 += __shfl_xor_sync(0xffffffff, s0, 2);
            q0 += __shfl_xor_sync(0xffffffff, q0, 1); q0 += __shfl_xor_sync(0xffffffff, q0, 2);
            s1 += __shfl_xor_sync(0xffffffff, s1, 1); s1 += __shfl_xor_sync(0xffffffff, s1, 2);
            q1 += __shfl_xor_sync(0xffffffff, q1, 1); q1 += __shfl_xor_sync(0xffffffff, q1, 2);
            if (lc == 0) {
                s_sum[wid & 3][r0l][0] = s0; s_sum[wid & 3][r0l][1] = q0;
                s_sum[wid & 3][r1l][0] = s1; s_sum[wid & 3][r1l][1] = q1;
            }
        }
    }
    if (STATS) {
        __syncthreads();
        if (tid < BM) {
            int gm = bm + tid;
            if (gm < M) {
                float s = s_sum[0][tid][0] + s_sum[1][tid][0] + s_sum[2][tid][0] + s_sum[3][tid][0];
                float q = s_sum[0][tid][1] + s_sum[1][tid][1] + s_sum[2][tid][1] + s_sum[3][tid][1];
                size_t nc = (size_t)nb * M + gm;
                psum[nc * MAXCOL + blockIdx.x] = s;
                psum2[nc * MAXCOL + blockIdx.x] = q;
            }
        }
    }
}

// ---------------- finalize stats (deterministic tree) ----------------
__global__ void finalize_stats_kernel(const float* __restrict__ ps,
                                      const float* __restrict__ ps2,
                                      float* __restrict__ mean, float* __restrict__ rstd,
                                      int ncol, int npix)
{
    int nc = blockIdx.x;
    double s = 0.0, s2 = 0.0;
    for (int j = threadIdx.x; j < ncol; j += 128) {
        s += (double)ps[(size_t)nc * MAXCOL + j];
        s2 += (double)ps2[(size_t)nc * MAXCOL + j];
    }
    __shared__ double sh[128], sh2[128];
    sh[threadIdx.x] = s; sh2[threadIdx.x] = s2;
    __syncthreads();
    for (int o = 64; o > 0; o >>= 1) {
        if (threadIdx.x < o) { sh[threadIdx.x] += sh[threadIdx.x + o]; sh2[threadIdx.x] += sh2[threadIdx.x + o]; }
        __syncthreads();
    }
    if (threadIdx.x == 0) {
        double mn = sh[0] / npix;
        double var = sh2[0] / npix - mn * mn;
        mean[nc] = (float)mn;
        rstd[nc] = (float)rsqrt(var + 1e-5);
    }
}

// ---------------- instance norm: apply ----------------
__global__ void norm_apply_kernel(const float* __restrict__ x,
                                  const float* __restrict__ mean,
                                  const float* __restrict__ rstd,
                                  const float* __restrict__ skip,
                                  float* __restrict__ out,
                                  int npix, int relu, size_t total)
{
    size_t i = (size_t)blockIdx.x * blockDim.x + threadIdx.x;
    if (i >= total) return;
    int nc = (int)(i / (size_t)npix);
    float v = (x[i] - mean[nc]) * rstd[nc];
    if (skip) v += skip[i];
    if (relu) v = fmaxf(v, 0.0f);
    out[i] = v;
}

// ---------------- launch ----------------
static inline int smem_for(int BM) { return (2 * BM * AS_STRIDE + 2 * BS_BUF) * 4; }

extern "C" void kernel_launch(void* const* d_in, const int* in_sizes, int n_in,
                              void* d_out, int out_size)
{
    (void)in_sizes; (void)n_in; (void)out_size;
    const float* x      = (const float*)d_in[0];
    const float* off1_w = (const float*)d_in[1];
    const float* off1_b = (const float*)d_in[2];
    const float* dcn1_w = (const float*)d_in[3];
    const float* dcn1_b = (const float*)d_in[4];
    const float* off2_w = (const float*)d_in[5];
    const float* off2_b = (const float*)d_in[6];
    const float* dcn2_w = (const float*)d_in[7];
    const float* dcn2_b = (const float*)d_in[8];
    const float* off3_w = (const float*)d_in[9];
    const float* off3_b = (const float*)d_in[10];
    const float* dcn3_w = (const float*)d_in[11];
    const float* dcn3_b = (const float*)d_in[12];
    const float* rb1_w1 = (const float*)d_in[13];
    const float* rb1_b1 = (const float*)d_in[14];
    const float* rb1_w2 = (const float*)d_in[15];
    const float* rb1_b2 = (const float*)d_in[16];
    const float* rb2_w1 = (const float*)d_in[17];
    const float* rb2_b1 = (const float*)d_in[18];
    const float* rb2_w2 = (const float*)d_in[19];
    const float* rb2_b2 = (const float*)d_in[20];

    float* outp  = (float*)d_out;
    float* out_h = outp;
    float* skip1 = outp + 2097152;
    float* skip2 = outp + 2097152 + 8388608;

    float *col, *offb, *tmp, *ga, *gb, *mn, *rs, *wpad, *psum, *psum2;
    cudaGetSymbolAddress((void**)&col,  g_col);
    cudaGetSymbolAddress((void**)&offb, g_off);
    cudaGetSymbolAddress((void**)&tmp,  g_tmp);
    cudaGetSymbolAddress((void**)&ga,   g_a);
    cudaGetSymbolAddress((void**)&gb,   g_b);
    cudaGetSymbolAddress((void**)&mn,   g_mean);
    cudaGetSymbolAddress((void**)&rs,   g_rstd);
    cudaGetSymbolAddress((void**)&wpad, g_wpad);
    cudaGetSymbolAddress((void**)&psum, g_psum);
    cudaGetSymbolAddress((void**)&psum2, g_psum2);
    float* off1p = wpad;
    float* dcn1p = wpad + 147 * 160;

    static bool attr_set = false;
    if (!attr_set) {
        cudaFuncSetAttribute((const void*)gemm_conv_kernel<64, 0, true>,   cudaFuncAttributeMaxDynamicSharedMemorySize, smem_for(64));
        cudaFuncSetAttribute((const void*)gemm_conv_kernel<128, 0, true>,  cudaFuncAttributeMaxDynamicSharedMemorySize, smem_for(128));
        cudaFuncSetAttribute((const void*)gemm_conv_kernel<64, 1, false>,  cudaFuncAttributeMaxDynamicSharedMemorySize, smem_for(64));
        cudaFuncSetAttribute((const void*)gemm_conv_kernel<128, 2, true>,  cudaFuncAttributeMaxDynamicSharedMemorySize, smem_for(128));
        attr_set = true;
    }

    ConvGeom g0 = {};

    auto dsample = [&](const float* src, const float* off, float* dst, int Cin, int H, int W,
                       int KH, int KW, int s, int p, int Ho, int Wo) {
        int npix = Ho * Wo;
        dim3 grid((npix + 255) / 256, KH * KW, 2);
        deform_sample_kernel<<<grid, 256>>>(src, off, dst, Cin, H, W, KH, KW, s, p, Ho, Wo);
    };
    // MODE 0 GEMM on col matrix (epilogue stats always on: only used for dcn convs)
    auto gemm_col = [&](const float* W, int lda, const float* B, const float* bias, float* C,
                        int M, int K, int N) {
        if (M <= 64) {
            dim3 grid(N / 128, 1, 2);
            gemm_conv_kernel<64, 0, true><<<grid, 256, smem_for(64)>>>(W, lda, B, bias, C, M, K, N, g0, psum, psum2);
        } else {
            dim3 grid(N / 128, (M + 127) / 128, 2);
            gemm_conv_kernel<128, 0, true><<<grid, 256, smem_for(128)>>>(W, lda, B, bias, C, M, K, N, g0, psum, psum2);
        }
    };
    // implicit conv, zero pad (offset convs — no stats needed)
    auto conv_zero = [&](const float* W, int lda, const float* X, const float* bias, float* C,
                         int M, int K, int N, ConvGeom g) {
        dim3 grid(N / 128, (M + 63) / 64, 2);
        gemm_conv_kernel<64, 1, false><<<grid, 256, smem_for(64)>>>(W, lda, X, bias, C, M, K, N, g, nullptr, nullptr);
    };
    // implicit conv, reflect pad (res blocks — stats on)
    auto conv_refl = [&](const float* W, int lda, const float* X, const float* bias, float* C,
                         int M, int K, int N, ConvGeom g) {
        dim3 grid(N / 128, (M + 127) / 128, 2);
        gemm_conv_kernel<128, 2, true><<<grid, 256, smem_for(128)>>>(W, lda, X, bias, C, M, K, N, g, psum, psum2);
    };
    auto inorm = [&](const float* xin, float* dst, int C, int npix, int ncol,
                     const float* skip, int relu) {
        finalize_stats_kernel<<<2 * C, 128>>>(psum, psum2, mn, rs, ncol, npix);
        size_t total = (size_t)2 * C * npix;
        norm_apply_kernel<<<(unsigned)((total + 255) / 256), 256>>>(xin, mn, rs, skip, dst, npix, relu, total);
    };

    // pack stage-1 weights (K=147 -> lda=160 for 16B-aligned cp.async)
    pad_weights_kernel<<<(147 * 160 + 255) / 256, 256>>>(off1_w, off1p, 147, 147, 160);
    pad_weights_kernel<<<(64 * 160 + 255) / 256, 256>>>(dcn1_w, dcn1p, 64, 147, 160);

    // ===== Stage 1: mdcp(x, 7x7, s1, p3), 3 -> 64, 256x256 =====
    ConvGeom g1 = {3, 256, 256, 7, 7, 49, 1, 3, 256};
    conv_zero(off1p, 160, x, off1_b, offb, 147, 147, 65536, g1);
    dsample(x, offb, col, 3, 256, 256, 7, 7, 1, 3, 256, 256);
    gemm_col(dcn1p, 160, col, dcn1_b, tmp, 64, 147, 65536);
    inorm(tmp, skip1, 64, 65536, 512, nullptr, 1);

    // ===== Stage 2: mdcp(h1, 4x4, s2, p1), 64 -> 128, 128x128 =====
    ConvGeom g2 = {64, 256, 256, 4, 4, 16, 2, 1, 128};
    conv_zero(off2_w, 1024, skip1, off2_b, offb, 48, 1024, 16384, g2);
    dsample(skip1, offb, col, 64, 256, 256, 4, 4, 2, 1, 128, 128);
    gemm_col(dcn2_w, 1024, col, dcn2_b, tmp, 128, 1024, 16384);
    inorm(tmp, skip2, 128, 16384, 128, nullptr, 1);

    // ===== Stage 3: mdcp(h2, 4x4, s2, p1), 128 -> 256, 64x64 =====
    ConvGeom g3 = {128, 128, 128, 4, 4, 16, 2, 1, 64};
    conv_zero(off3_w, 2048, skip2, off3_b, offb, 48, 2048, 4096, g3);
    dsample(skip2, offb, col, 128, 128, 128, 4, 4, 2, 1, 64, 64);
    gemm_col(dcn3_w, 2048, col, dcn3_b, tmp, 256, 2048, 4096);
    inorm(tmp, ga, 256, 4096, 32, nullptr, 1);

    // ===== Res blocks (reflect-pad 3x3 convs, 256 ch, 64x64, implicit) =====
    ConvGeom gr = {256, 64, 64, 3, 3, 9, 1, 1, 64};
    conv_refl(rb1_w1, 2304, ga, rb1_b1, tmp, 256, 2304, 4096, gr);
    inorm(tmp, gb, 256, 4096, 32, nullptr, 1);
    conv_refl(rb1_w2, 2304, gb, rb1_b2, tmp, 256, 2304, 4096, gr);
    inorm(tmp, ga, 256, 4096, 32, ga, 0);

    conv_refl(rb2_w1, 2304, ga, rb2_b1, tmp, 256, 2304, 4096, gr);
    inorm(tmp, gb, 256, 4096, 32, nullptr, 1);
    conv_refl(rb2_w2, 2304, gb, rb2_b2, tmp, 256, 2304, 4096, gr);
    inorm(tmp, out_h, 256, 4096, 32, ga, 0);
}

// round 7
// speedup vs baseline: 1.8434x; 1.3367x over previous
#include <cuda_runtime.h>
#include <cuda_fp16.h>
#include <math.h>
#include <stdint.h>

// ---------------- scratch (static device globals; no allocation) ----------------
__device__ float g_col[33554432];   // dsample cols (max stage2: 2*1024*16384)
__device__ float g_off[19267584];   // offset conv out (max stage1: 2*147*65536)
__device__ float g_tmp[8388608];    // pre-norm GEMM out (max stage1: 2*64*65536)
__device__ float g_a[2097152];
__device__ float g_b[2097152];
__device__ float g_mean[512];
__device__ float g_rstd[512];
__device__ float g_wpad[33760];     // stage-1 weights padded to lda=160
__device__ float g_psum[262144];    // per-(nc, colCTA) partial sums
__device__ float g_psum2[262144];

#define MAXCOL 512

// ---------------- deformable sampling -> column matrix ----------------
__global__ void deform_sample_kernel(const float* __restrict__ x,
                                     const float* __restrict__ off,
                                     float* __restrict__ col,
                                     int Cin, int H, int W, int KH, int KW,
                                     int stride, int pad, int Ho, int Wo)
{
    int npix = Ho * Wo;
    int pix = blockIdx.x * blockDim.x + threadIdx.x;
    if (pix >= npix) return;
    int K = KH * KW;
    int k = blockIdx.y;
    int n = blockIdx.z;
    int ho = pix / Wo, wo = pix % Wo;

    const float* offn = off + (size_t)n * 3 * K * npix;
    float oy = offn[(size_t)k * npix + pix];
    float ox = offn[(size_t)(K + k) * npix + pix];
    float ml = offn[(size_t)(2 * K + k) * npix + pix];
    float m = 1.0f / (1.0f + expf(-ml));

    int ky = k / KW, kx = k % KW;
    float py = (float)(ho * stride - pad + ky) + oy;
    float px = (float)(wo * stride - pad + kx) + ox;
    float y0f = floorf(py), x0f = floorf(px);
    int y0 = (int)y0f, x0 = (int)x0f;
    float wy = py - y0f, wx = px - x0f;

    int y1 = y0 + 1, x1 = x0 + 1;
    float vy0 = (y0 >= 0 && y0 <= H - 1) ? 1.0f : 0.0f;
    float vy1 = (y1 >= 0 && y1 <= H - 1) ? 1.0f : 0.0f;
    float vx0 = (x0 >= 0 && x0 <= W - 1) ? 1.0f : 0.0f;
    float vx1 = (x1 >= 0 && x1 <= W - 1) ? 1.0f : 0.0f;
    int y0c = min(max(y0, 0), H - 1), y1c = min(max(y1, 0), H - 1);
    int x0c = min(max(x0, 0), W - 1), x1c = min(max(x1, 0), W - 1);

    float w00 = (1.0f - wy) * (1.0f - wx) * vy0 * vx0 * m;
    float w01 = (1.0f - wy) * wx          * vy0 * vx1 * m;
    float w10 = wy          * (1.0f - wx) * vy1 * vx0 * m;
    float w11 = wy          * wx          * vy1 * vx1 * m;

    size_t b00 = (size_t)y0c * W + x0c;
    size_t b01 = (size_t)y0c * W + x1c;
    size_t b10 = (size_t)y1c * W + x0c;
    size_t b11 = (size_t)y1c * W + x1c;

    const float* xn = x + (size_t)n * Cin * H * W;
    float* cp = col + (size_t)n * Cin * K * npix + (size_t)k * npix + pix;
    size_t cstride = (size_t)K * npix;
    for (int c = 0; c < Cin; c++) {
        const float* xc = xn + (size_t)c * H * W;
        float v = w00 * xc[b00] + w01 * xc[b01] + w10 * xc[b10] + w11 * xc[b11];
        cp[(size_t)c * cstride] = v;
    }
}

// ---------------- weight padding (stage 1: K=147 -> lda=160) ----------------
__global__ void pad_weights_kernel(const float* __restrict__ w, float* __restrict__ wp,
                                   int M, int K, int Kp)
{
    int idx = blockIdx.x * blockDim.x + threadIdx.x;
    if (idx >= M * Kp) return;
    int m = idx / Kp, k = idx % Kp;
    wp[idx] = (k < K) ? w[m * K + k] : 0.0f;
}

// ---------------- fp16x3 implicit-conv / GEMM kernel ----------------
// MODE 0: B = precomputed col matrix [n][K][N]
// MODE 1: implicit conv, zero padding  (B = input tensor NCHW)
// MODE 2: implicit conv, reflect padding
struct ConvGeom { int Cin, H, W, KH, KW, KKW, stride, pad, Wo; };

// split pair (a = k-element, b = k+1-element) into packed fp16 hi/lo halves:
// value = hi + lo to ~22-bit precision; hi in low 16 bits = element k.
__device__ __forceinline__ void split_h2(float a, float b, uint32_t& hi, uint32_t& lo) {
    __half ha = __float2half_rn(a), hb = __float2half_rn(b);
    float ra = a - __half2float(ha), rb = b - __half2float(hb);
    __half2 H = __halves2half2(ha, hb);
    __half2 L = __halves2half2(__float2half_rn(ra), __float2half_rn(rb));
    hi = *reinterpret_cast<uint32_t*>(&H);
    lo = *reinterpret_cast<uint32_t*>(&L);
}

#define AS_STRIDE 40      // conflict-free float2 k-pair fragment loads
#define BS_STRIDE 132     // bank = (8*lc + lr + c) mod 32 -> all distinct
#define BS_BUF (32 * BS_STRIDE)

extern __shared__ float smem_dyn[];

#define MMA_F16(acc, a0, a1, a2, a3, b0, b1)                                   \
    asm volatile(                                                              \
        "mma.sync.aligned.m16n8k16.row.col.f32.f16.f16.f32 "                   \
        "{%0,%1,%2,%3}, {%4,%5,%6,%7}, {%8,%9}, {%0,%1,%2,%3};\n"              \
        : "+f"(acc[0]), "+f"(acc[1]), "+f"(acc[2]), "+f"(acc[3])               \
        : "r"(a0), "r"(a1), "r"(a2), "r"(a3), "r"(b0), "r"(b1))

template <int BM, int MODE, bool STATS>
__global__ void __launch_bounds__(256, 1)
gemm_conv_kernel(const float* __restrict__ A, int lda,
                 const float* __restrict__ B,
                 const float* __restrict__ bias,
                 float* __restrict__ C,
                 int M, int Kd, int N, ConvGeom g,
                 float* __restrict__ psum, float* __restrict__ psum2)
{
    constexpr int AS_BUF = BM * AS_STRIDE;
    constexpr int IMAX = BM / 32;
    float* As = smem_dyn;
    float* Bs = smem_dyn + 2 * AS_BUF;
    constexpr int SW = STATS ? 4 : 1;
    __shared__ float s_sum[SW][BM][2];

    int nb = blockIdx.z;
    float* Cn = C + (size_t)nb * M * N;
    int bm = blockIdx.y * BM, bn = blockIdx.x * 128;
    int tid = threadIdx.x;
    int wid = tid >> 5, lane = tid & 31;
    int warp_m = (wid >> 2) * (BM / 2);
    int warp_n = (wid & 3) * 32;
    int lr = lane >> 2, lc = lane & 3;

    float acc[IMAX][4][4];
#pragma unroll
    for (int i = 0; i < IMAX; i++)
#pragma unroll
        for (int j = 0; j < 4; j++)
#pragma unroll
            for (int q = 0; q < 4; q++) acc[i][j][q] = 0.0f;

    int nk = (Kd + 31) / 32;

    auto loadA = [&](int kt, int s) {
        int k0 = kt * 32;
        constexpr int ACP = BM / 32;
#pragma unroll
        for (int t = 0; t < ACP; t++) {
            int idx = tid + t * 256;
            int m = idx >> 3;
            int k4 = (idx & 7) << 2;
            int gm = bm + m, gk = k0 + k4;
            const float* src = A + (size_t)gm * lda + gk;
            float* dst = As + s * AS_BUF + m * AS_STRIDE + k4;
            int bytes = (gm < M && gk < Kd) ? min(16, (Kd - gk) * 4) : 0;
            uint32_t sa = (uint32_t)__cvta_generic_to_shared(dst);
            asm volatile("cp.async.ca.shared.global [%0], [%1], 16, %2;\n"
                         :: "r"(sa), "l"(src), "r"(bytes));
        }
    };

    auto loadB_col = [&](int kt, int s) {
        const float* Bn = B + (size_t)nb * Kd * N;
        int k0 = kt * 32;
#pragma unroll
        for (int t = 0; t < 4; t++) {
            int idx = tid + t * 256;
            int k = idx >> 5;
            int n4 = (idx & 31) << 2;
            int gk = k0 + k;
            const float* src = Bn + (size_t)gk * N + bn + n4;
            float* dst = Bs + s * BS_BUF + k * BS_STRIDE + n4;
            int bytes = (gk < Kd) ? 16 : 0;
            uint32_t sa = (uint32_t)__cvta_generic_to_shared(dst);
            asm volatile("cp.async.ca.shared.global [%0], [%1], 16, %2;\n"
                         :: "r"(sa), "l"(src), "r"(bytes));
        }
    };

    // gather B tile (implicit conv): thread -> one k-row, 16 contiguous columns
    auto gatherB = [&](int kt, float* pref) {
        int k_l = tid >> 3;
        int cb = (tid & 7) << 4;
        int gk = kt * 32 + k_l;
        bool kv = gk < Kd;
        int kk = kv ? gk : 0;
        int c = kk / g.KKW;
        int r = kk - c * g.KKW;
        int ky = r / g.KW;
        int kx = r - ky * g.KW;
        int pix = bn + cb;
        int ho = pix / g.Wo;
        int wo = pix - ho * g.Wo;
        int iy = ho * g.stride - g.pad + ky;
        int ix0 = wo * g.stride - g.pad + kx;
        const float* xc = B + ((size_t)nb * g.Cin + c) * g.H * g.W;
        if (MODE == 2) {
            if (iy < 0) iy = -iy; else if (iy >= g.H) iy = 2 * g.H - 2 - iy;
            const float* rowp = xc + (size_t)iy * g.W;
#pragma unroll
            for (int i = 0; i < 16; i++) {
                int ix = ix0 + i * g.stride;
                if (ix < 0) ix = -ix; else if (ix >= g.W) ix = 2 * g.W - 2 - ix;
                pref[i] = kv ? __ldg(rowp + ix) : 0.0f;
            }
        } else {
            bool rok = kv && iy >= 0 && iy < g.H;
            const float* rowp = xc + (size_t)max(iy, 0) * g.W;
#pragma unroll
            for (int i = 0; i < 16; i++) {
                int ix = ix0 + i * g.stride;
                pref[i] = (rok && ix >= 0 && ix < g.W) ? __ldg(rowp + ix) : 0.0f;
            }
        }
    };
    auto stsB = [&](const float* pref, int s) {
        int k_l = tid >> 3;
        int cb = (tid & 7) << 4;
        float* dst = Bs + s * BS_BUF + k_l * BS_STRIDE + cb;
#pragma unroll
        for (int i = 0; i < 16; i++) dst[i] = pref[i];
    };

    loadA(0, 0);
    if (MODE == 0) {
        loadB_col(0, 0);
    } else {
        float pref[16];
        gatherB(0, pref);
        stsB(pref, 0);
    }
    asm volatile("cp.async.commit_group;\n");

    for (int kt = 0; kt < nk; kt++) {
        int s = kt & 1;
        float pref[16];
        bool do_pref = (kt + 1 < nk);
        if (do_pref) {
            loadA(kt + 1, s ^ 1);
            if (MODE == 0) loadB_col(kt + 1, s ^ 1);
            asm volatile("cp.async.commit_group;\n");
            if (MODE != 0) gatherB(kt + 1, pref);
            asm volatile("cp.async.wait_group 1;\n");
        } else {
            asm volatile("cp.async.wait_group 0;\n");
        }
        __syncthreads();

        const float* Asb = As + s * AS_BUF;
        const float* Bsb = Bs + s * BS_BUF;
#pragma unroll
        for (int ks = 0; ks < 2; ks++) {     // two k16 steps per 32-k tile
            uint32_t ah[IMAX][4], al[IMAX][4], bh[4][2], bl[4][2];
#pragma unroll
            for (int i = 0; i < IMAX; i++) {
                const float* ap = Asb + (warp_m + i * 16 + lr) * AS_STRIDE + ks * 16 + 2 * lc;
                float2 v00 = *(const float2*)ap;                       // row lr,   k,k+1
                float2 v10 = *(const float2*)(ap + 8 * AS_STRIDE);     // row lr+8, k,k+1
                float2 v01 = *(const float2*)(ap + 8);                 // row lr,   k+8,k+9
                float2 v11 = *(const float2*)(ap + 8 * AS_STRIDE + 8); // row lr+8, k+8,k+9
                split_h2(v00.x, v00.y, ah[i][0], al[i][0]);
                split_h2(v10.x, v10.y, ah[i][1], al[i][1]);
                split_h2(v01.x, v01.y, ah[i][2], al[i][2]);
                split_h2(v11.x, v11.y, ah[i][3], al[i][3]);
            }
#pragma unroll
            for (int j = 0; j < 4; j++) {
                const float* bp = Bsb + (ks * 16 + 2 * lc) * BS_STRIDE + warp_n + j * 8 + lr;
                float e0 = bp[0];
                float e1 = bp[BS_STRIDE];
                float e2 = bp[8 * BS_STRIDE];
                float e3 = bp[9 * BS_STRIDE];
                split_h2(e0, e1, bh[j][0], bl[j][0]);
                split_h2(e2, e3, bh[j][1], bl[j][1]);
            }
#pragma unroll
            for (int i = 0; i < IMAX; i++)
#pragma unroll
                for (int j = 0; j < 4; j++) {
                    MMA_F16(acc[i][j], ah[i][0], ah[i][1], ah[i][2], ah[i][3],
                            bl[j][0], bl[j][1]);
                    MMA_F16(acc[i][j], al[i][0], al[i][1], al[i][2], al[i][3],
                            bh[j][0], bh[j][1]);
                    MMA_F16(acc[i][j], ah[i][0], ah[i][1], ah[i][2], ah[i][3],
                            bh[j][0], bh[j][1]);
                }
        }
        if (MODE != 0 && do_pref) stsB(pref, s ^ 1);
        __syncthreads();
    }

    // ---- epilogue: bias + store (+ optional per-row partial stats) ----
#pragma unroll
    for (int i = 0; i < IMAX; i++) {
        int r0l = warp_m + i * 16 + lr;
        int r1l = r0l + 8;
        int gr0 = bm + r0l, gr1 = bm + r1l;
        float bv0 = (gr0 < M) ? bias[gr0] : 0.0f;
        float bv1 = (gr1 < M) ? bias[gr1] : 0.0f;
        float s0 = 0, q0 = 0, s1 = 0, q1 = 0;
#pragma unroll
        for (int j = 0; j < 4; j++) {
            int cidx = bn + warp_n + j * 8 + lc * 2;
            float v0 = acc[i][j][0] + bv0, v1 = acc[i][j][1] + bv0;
            float v2 = acc[i][j][2] + bv1, v3 = acc[i][j][3] + bv1;
            if (gr0 < M) *(float2*)&Cn[(size_t)gr0 * N + cidx] = make_float2(v0, v1);
            if (gr1 < M) *(float2*)&Cn[(size_t)gr1 * N + cidx] = make_float2(v2, v3);
            if (STATS) {
                s0 += v0 + v1; q0 += v0 * v0 + v1 * v1;
                s1 += v2 + v3; q1 += v2 * v2 + v3 * v3;
            }
        }
        if (STATS) {
            s0 += __shfl_xor_sync(0xffffffff, s0, 1); s0 += __shfl_xor_sync(0xffffffff, s0, 2);
            q0 += __shfl_xor_sync(0xffffffff, q0, 1); q0 += __shfl_xor_sync(0xffffffff, q0, 2);
            s1 += __shfl_xor_sync(0xffffffff, s1, 1); s1 += __shfl_xor_sync(0xffffffff, s1, 2);
            q1 += __shfl_xor_sync(0xffffffff, q1, 1); q1 += __shfl_xor_sync(0xffffffff, q1, 2);
            if (lc == 0) {
                s_sum[wid & 3][r0l][0] = s0; s_sum[wid & 3][r0l][1] = q0;
                s_sum[wid & 3][r1l][0] = s1; s_sum[wid & 3][r1l][1] = q1;
            }
        }
    }
    if (STATS) {
        __syncthreads();
        if (tid < BM) {
            int gm = bm + tid;
            if (gm < M) {
                float s = s_sum[0][tid][0] + s_sum[1][tid][0] + s_sum[2][tid][0] + s_sum[3][tid][0];
                float q = s_sum[0][tid][1] + s_sum[1][tid][1] + s_sum[2][tid][1] + s_sum[3][tid][1];
                size_t nc = (size_t)nb * M + gm;
                psum[nc * MAXCOL + blockIdx.x] = s;
                psum2[nc * MAXCOL + blockIdx.x] = q;
            }
        }
    }
}

// ---------------- finalize stats (deterministic tree) ----------------
__global__ void finalize_stats_kernel(const float* __restrict__ ps,
                                      const float* __restrict__ ps2,
                                      float* __restrict__ mean, float* __restrict__ rstd,
                                      int ncol, int npix)
{
    int nc = blockIdx.x;
    double s = 0.0, s2 = 0.0;
    for (int j = threadIdx.x; j < ncol; j += 128) {
        s += (double)ps[(size_t)nc * MAXCOL + j];
        s2 += (double)ps2[(size_t)nc * MAXCOL + j];
    }
    __shared__ double sh[128], sh2[128];
    sh[threadIdx.x] = s; sh2[threadIdx.x] = s2;
    __syncthreads();
    for (int o = 64; o > 0; o >>= 1) {
        if (threadIdx.x < o) { sh[threadIdx.x] += sh[threadIdx.x + o]; sh2[threadIdx.x] += sh2[threadIdx.x + o]; }
        __syncthreads();
    }
    if (threadIdx.x == 0) {
        double mn = sh[0] / npix;
        double var = sh2[0] / npix - mn * mn;
        mean[nc] = (float)mn;
        rstd[nc] = (float)rsqrt(var + 1e-5);
    }
}

// ---------------- instance norm: apply ----------------
__global__ void norm_apply_kernel(const float* __restrict__ x,
                                  const float* __restrict__ mean,
                                  const float* __restrict__ rstd,
                                  const float* __restrict__ skip,
                                  float* __restrict__ out,
                                  int npix, int relu, size_t total)
{
    size_t i = (size_t)blockIdx.x * blockDim.x + threadIdx.x;
    if (i >= total) return;
    int nc = (int)(i / (size_t)npix);
    float v = (x[i] - mean[nc]) * rstd[nc];
    if (skip) v += skip[i];
    if (relu) v = fmaxf(v, 0.0f);
    out[i] = v;
}

// ---------------- launch ----------------
static inline int smem_for(int BM) { return (2 * BM * AS_STRIDE + 2 * BS_BUF) * 4; }

extern "C" void kernel_launch(void* const* d_in, const int* in_sizes, int n_in,
                              void* d_out, int out_size)
{
    (void)in_sizes; (void)n_in; (void)out_size;
    const float* x      = (const float*)d_in[0];
    const float* off1_w = (const float*)d_in[1];
    const float* off1_b = (const float*)d_in[2];
    const float* dcn1_w = (const float*)d_in[3];
    const float* dcn1_b = (const float*)d_in[4];
    const float* off2_w = (const float*)d_in[5];
    const float* off2_b = (const float*)d_in[6];
    const float* dcn2_w = (const float*)d_in[7];
    const float* dcn2_b = (const float*)d_in[8];
    const float* off3_w = (const float*)d_in[9];
    const float* off3_b = (const float*)d_in[10];
    const float* dcn3_w = (const float*)d_in[11];
    const float* dcn3_b = (const float*)d_in[12];
    const float* rb1_w1 = (const float*)d_in[13];
    const float* rb1_b1 = (const float*)d_in[14];
    const float* rb1_w2 = (const float*)d_in[15];
    const float* rb1_b2 = (const float*)d_in[16];
    const float* rb2_w1 = (const float*)d_in[17];
    const float* rb2_b1 = (const float*)d_in[18];
    const float* rb2_w2 = (const float*)d_in[19];
    const float* rb2_b2 = (const float*)d_in[20];

    float* outp  = (float*)d_out;
    float* out_h = outp;
    float* skip1 = outp + 2097152;
    float* skip2 = outp + 2097152 + 8388608;

    float *col, *offb, *tmp, *ga, *gb, *mn, *rs, *wpad, *psum, *psum2;
    cudaGetSymbolAddress((void**)&col,  g_col);
    cudaGetSymbolAddress((void**)&offb, g_off);
    cudaGetSymbolAddress((void**)&tmp,  g_tmp);
    cudaGetSymbolAddress((void**)&ga,   g_a);
    cudaGetSymbolAddress((void**)&gb,   g_b);
    cudaGetSymbolAddress((void**)&mn,   g_mean);
    cudaGetSymbolAddress((void**)&rs,   g_rstd);
    cudaGetSymbolAddress((void**)&wpad, g_wpad);
    cudaGetSymbolAddress((void**)&psum, g_psum);
    cudaGetSymbolAddress((void**)&psum2, g_psum2);
    float* off1p = wpad;
    float* dcn1p = wpad + 147 * 160;

    static bool attr_set = false;
    if (!attr_set) {
        cudaFuncSetAttribute((const void*)gemm_conv_kernel<64, 0, true>,   cudaFuncAttributeMaxDynamicSharedMemorySize, smem_for(64));
        cudaFuncSetAttribute((const void*)gemm_conv_kernel<128, 0, true>,  cudaFuncAttributeMaxDynamicSharedMemorySize, smem_for(128));
        cudaFuncSetAttribute((const void*)gemm_conv_kernel<64, 1, false>,  cudaFuncAttributeMaxDynamicSharedMemorySize, smem_for(64));
        cudaFuncSetAttribute((const void*)gemm_conv_kernel<128, 2, true>,  cudaFuncAttributeMaxDynamicSharedMemorySize, smem_for(128));
        attr_set = true;
    }

    ConvGeom g0 = {};

    auto dsample = [&](const float* src, const float* off, float* dst, int Cin, int H, int W,
                       int KH, int KW, int s, int p, int Ho, int Wo) {
        int npix = Ho * Wo;
        dim3 grid((npix + 255) / 256, KH * KW, 2);
        deform_sample_kernel<<<grid, 256>>>(src, off, dst, Cin, H, W, KH, KW, s, p, Ho, Wo);
    };
    auto gemm_col = [&](const float* W, int lda, const float* B, const float* bias, float* C,
                        int M, int K, int N) {
        if (M <= 64) {
            dim3 grid(N / 128, 1, 2);
            gemm_conv_kernel<64, 0, true><<<grid, 256, smem_for(64)>>>(W, lda, B, bias, C, M, K, N, g0, psum, psum2);
        } else {
            dim3 grid(N / 128, (M + 127) / 128, 2);
            gemm_conv_kernel<128, 0, true><<<grid, 256, smem_for(128)>>>(W, lda, B, bias, C, M, K, N, g0, psum, psum2);
        }
    };
    auto conv_zero = [&](const float* W, int lda, const float* X, const float* bias, float* C,
                         int M, int K, int N, ConvGeom g) {
        dim3 grid(N / 128, (M + 63) / 64, 2);
        gemm_conv_kernel<64, 1, false><<<grid, 256, smem_for(64)>>>(W, lda, X, bias, C, M, K, N, g, nullptr, nullptr);
    };
    auto conv_refl = [&](const float* W, int lda, const float* X, const float* bias, float* C,
                         int M, int K, int N, ConvGeom g) {
        dim3 grid(N / 128, (M + 127) / 128, 2);
        gemm_conv_kernel<128, 2, true><<<grid, 256, smem_for(128)>>>(W, lda, X, bias, C, M, K, N, g, psum, psum2);
    };
    auto inorm = [&](const float* xin, float* dst, int C, int npix, int ncol,
                     const float* skip, int relu) {
        finalize_stats_kernel<<<2 * C, 128>>>(psum, psum2, mn, rs, ncol, npix);
        size_t total = (size_t)2 * C * npix;
        norm_apply_kernel<<<(unsigned)((total + 255) / 256), 256>>>(xin, mn, rs, skip, dst, npix, relu, total);
    };

    // pack stage-1 weights (K=147 -> lda=160 for 16B-aligned cp.async)
    pad_weights_kernel<<<(147 * 160 + 255) / 256, 256>>>(off1_w, off1p, 147, 147, 160);
    pad_weights_kernel<<<(64 * 160 + 255) / 256, 256>>>(dcn1_w, dcn1p, 64, 147, 160);

    // ===== Stage 1: mdcp(x, 7x7, s1, p3), 3 -> 64, 256x256 =====
    ConvGeom g1 = {3, 256, 256, 7, 7, 49, 1, 3, 256};
    conv_zero(off1p, 160, x, off1_b, offb, 147, 147, 65536, g1);
    dsample(x, offb, col, 3, 256, 256, 7, 7, 1, 3, 256, 256);
    gemm_col(dcn1p, 160, col, dcn1_b, tmp, 64, 147, 65536);
    inorm(tmp, skip1, 64, 65536, 512, nullptr, 1);

    // ===== Stage 2: mdcp(h1, 4x4, s2, p1), 64 -> 128, 128x128 =====
    ConvGeom g2 = {64, 256, 256, 4, 4, 16, 2, 1, 128};
    conv_zero(off2_w, 1024, skip1, off2_b, offb, 48, 1024, 16384, g2);
    dsample(skip1, offb, col, 64, 256, 256, 4, 4, 2, 1, 128, 128);
    gemm_col(dcn2_w, 1024, col, dcn2_b, tmp, 128, 1024, 16384);
    inorm(tmp, skip2, 128, 16384, 128, nullptr, 1);

    // ===== Stage 3: mdcp(h2, 4x4, s2, p1), 128 -> 256, 64x64 =====
    ConvGeom g3 = {128, 128, 128, 4, 4, 16, 2, 1, 64};
    conv_zero(off3_w, 2048, skip2, off3_b, offb, 48, 2048, 4096, g3);
    dsample(skip2, offb, col, 128, 128, 128, 4, 4, 2, 1, 64, 64);
    gemm_col(dcn3_w, 2048, col, dcn3_b, tmp, 256, 2048, 4096);
    inorm(tmp, ga, 256, 4096, 32, nullptr, 1);

    // ===== Res blocks (reflect-pad 3x3 convs, 256 ch, 64x64, implicit) =====
    ConvGeom gr = {256, 64, 64, 3, 3, 9, 1, 1, 64};
    conv_refl(rb1_w1, 2304, ga, rb1_b1, tmp, 256, 2304, 4096, gr);
    inorm(tmp, gb, 256, 4096, 32, nullptr, 1);
    conv_refl(rb1_w2, 2304, gb, rb1_b2, tmp, 256, 2304, 4096, gr);
    inorm(tmp, ga, 256, 4096, 32, ga, 0);

    conv_refl(rb2_w1, 2304, ga, rb2_b1, tmp, 256, 2304, 4096, gr);
    inorm(tmp, gb, 256, 4096, 32, nullptr, 1);
    conv_refl(rb2_w2, 2304, gb, rb2_b2, tmp, 256, 2304, 4096, gr);
    inorm(tmp, out_h, 256, 4096, 32, ga, 0);
}